// round 16
// baseline (speedup 1.0000x reference)
#include <cuda_runtime.h>
#include <math.h>

// Problem constants (SPINN1: B=128, T=40, D_HID=512, D_TRK=256)
#define BB   128
#define TT   40
#define DD   512
#define TRK  256
#define CAP  (TT + 2)            // 42
#define TWOD (2 * DD)            // 1024
#define KIH  (3 * DD)            // 1536  (xIc = [buf_h | s1_h | s2_h])
#define NTRK (4 * TRK)           // 1024
#define KRED (2 * DD + TRK)      // 1280  (xRc row = [s2_h | s1_h | th_new])
#define NRED (5 * DD)            // 2560
#define SPI  8                   // W_ih compact GEMM split-K (12 slabs each)
#define SPH  2                   // W_hh GEMM split-K (8 slabs each)
#define SPLIT_RED 5              // reduce split-K (16 slabs each)
#define NB_I (8 * SPI * 2)       // 128 IH blocks (2 m-strips, early-exit)
#define NB_H (8 * SPH * 2)       // 32 HH blocks
#define NB_G (NB_I + NB_H)       // 160
#define MAXSTEPS 64

// ---------------- device state (no runtime allocation allowed) --------------
__device__ __align__(16) float g_stack[BB * CAP * TWOD];
__device__ __align__(16) float g_th[BB * TRK];
__device__ __align__(16) float g_tc[BB * TRK];
__device__ int   g_sptr[BB];
__device__ int   g_blen[BB];
__device__ __align__(16) float g_xIc[BB * KIH];           // COMPACTED changed rows
__device__ __align__(16) float g_xRc[BB * KRED];          // COMPACTED reduce rows
__device__ __align__(16) float g_gih[BB * NTRK];          // cached W_ih . x per row
__device__ __align__(16) float g_partI[SPI * BB * NTRK];
__device__ __align__(16) float g_partH[SPH * BB * NTRK];
__device__ __align__(16) float g_partRc[SPLIT_RED * BB * NRED];
__device__ int   g_trans[BB];
__device__ int   g_redidx[BB];                            // reduce compact idx or -1
__device__ int   g_chgidx[BB];                            // changed compact idx or -1
__device__ unsigned g_redcnt[MAXSTEPS];
__device__ unsigned g_chgcnt[MAXSTEPS + 1];
__device__ __align__(16) float g_Wih[NTRK * KIH];
__device__ __align__(16) float g_Whh[NTRK * TRK];
__device__ __align__(16) float g_Wred[NRED * KRED];  // [W_left | W_right | W_track]
__device__ __align__(16) float g_btrk[NTRK];         // b_ih + b_hh

__device__ __forceinline__ float sigf(float x) { return 1.0f / (1.0f + expf(-x)); }

typedef unsigned long long ull;
__device__ __forceinline__ ull packf2(float x, float y) {
    ull v; asm("mov.b64 %0, {%1,%2};" : "=l"(v) : "f"(x), "f"(y)); return v;
}
__device__ __forceinline__ float2 unpackf2(ull v) {
    float2 r; asm("mov.b64 {%0,%1}, %2;" : "=f"(r.x), "=f"(r.y) : "l"(v)); return r;
}
__device__ __forceinline__ void ffma2(ull& d, ull a, ull b) {
    asm("fma.rn.f32x2 %0, %1, %2, %0;" : "+l"(d) : "l"(a), "l"(b));
}

// ---------------- init -------------------------------------------------------
__global__ void k_init(const float* __restrict__ buffers,
                       const float* __restrict__ W_ih, const float* __restrict__ W_hh,
                       const float* __restrict__ b_ih, const float* __restrict__ b_hh,
                       const float* __restrict__ W_left, const float* __restrict__ W_right,
                       const float* __restrict__ W_track) {
    int stride = gridDim.x * blockDim.x;
    int tid0 = blockIdx.x * blockDim.x + threadIdx.x;

    for (int idx = tid0; idx < NTRK * KIH; idx += stride) g_Wih[idx] = W_ih[idx];
    for (int idx = tid0; idx < NTRK * TRK; idx += stride) g_Whh[idx] = W_hh[idx];
    for (int idx = tid0; idx < NRED * KRED; idx += stride) {
        int n = idx / KRED, k = idx - n * KRED;
        float v;
        if (k < DD)            v = W_left[n * DD + k];
        else if (k < 2 * DD)   v = W_right[n * DD + (k - DD)];
        else                   v = W_track[n * TRK + (k - 2 * DD)];
        g_Wred[idx] = v;
    }
    for (int idx = tid0; idx < NTRK; idx += stride) g_btrk[idx] = b_ih[idx] + b_hh[idx];
    for (int idx = tid0; idx < BB * TWOD; idx += stride) {
        int b = idx / TWOD, j = idx - b * TWOD;
        float v = buffers[(long)b * TT * TWOD + j];   // buffers[b, 0, j]
        g_stack[((long)b * CAP + 0) * TWOD + j] = v;
        g_stack[((long)b * CAP + 1) * TWOD + j] = v;
    }
    for (int idx = tid0; idx < BB * TRK; idx += stride) { g_th[idx] = 0.f; g_tc[idx] = 0.f; }
    for (int idx = tid0; idx < BB; idx += stride) {
        g_sptr[idx] = 2; g_blen[idx] = TT; g_redidx[idx] = -1; g_chgidx[idx] = -1;
    }
    for (int idx = tid0; idx < MAXSTEPS; idx += stride) g_redcnt[idx] = 0u;
    for (int idx = tid0; idx <= MAXSTEPS; idx += stride) g_chgcnt[idx] = 0u;
}

// ---------------- prep: step 0 treats every row as changed ------------------
__global__ void k_prep(const float* __restrict__ buffers) {
    int b = blockIdx.x, tid = threadIdx.x;    // 512 threads
    int sptr = g_sptr[b], blen = g_blen[b];
    const float* bt = buffers + ((long)b * TT + (blen - 1)) * TWOD;
    const float* s1 = g_stack + ((long)b * CAP + (sptr - 1)) * TWOD;
    const float* s2 = g_stack + ((long)b * CAP + (sptr - 2)) * TWOD;
    float* xi = g_xIc + (size_t)b * KIH;      // compact idx = b at step 0
    xi[tid] = bt[tid]; xi[DD + tid] = s1[tid]; xi[2 * DD + tid] = s2[tid];
    if (tid == 0) { g_chgidx[b] = b; g_chgcnt[0] = (unsigned)BB; }
}

// ---------------- BM=64 GEMM tile (128 thr, 8x8 microtile, fp32x2) ----------
__device__ __forceinline__ void gemm64(const float* __restrict__ A, int lda,
                                       const float* __restrict__ W, int ldw,
                                       float* __restrict__ Cp, int N,
                                       int mBase, int nBase, int kBase, int iters) {
    __shared__ __align__(16) float As[2][16][64];
    __shared__ __align__(16) float Ws[2][16][128];
    int tid = threadIdx.x;           // 128 threads
    int tm = (tid & 7) * 8;          // 8 m-groups
    int tn = (tid >> 3) * 8;         // 16 n-groups
    int row4 = tid >> 2;
    int lk   = (tid & 3) * 4;

    ull acc[32];
    #pragma unroll
    for (int i = 0; i < 32; i++) acc[i] = 0ull;

    auto ldg_store = [&](int buf, int k0) {
        #pragma unroll
        for (int r = 0; r < 2; r++) {      // A: 64 rows
            int row = row4 + r * 32;
            float4 v = *(const float4*)(A + (long)(mBase + row) * lda + k0 + lk);
            As[buf][lk + 0][row] = v.x; As[buf][lk + 1][row] = v.y;
            As[buf][lk + 2][row] = v.z; As[buf][lk + 3][row] = v.w;
        }
        #pragma unroll
        for (int r = 0; r < 4; r++) {      // W: 128 rows
            int row = row4 + r * 32;
            float4 v = *(const float4*)(W + (long)(nBase + row) * ldw + k0 + lk);
            Ws[buf][lk + 0][row] = v.x; Ws[buf][lk + 1][row] = v.y;
            Ws[buf][lk + 2][row] = v.z; Ws[buf][lk + 3][row] = v.w;
        }
    };

    ldg_store(0, kBase);
    __syncthreads();

    for (int it = 0; it < iters; it++) {
        int buf = it & 1;
        bool more = (it + 1) < iters;
        #pragma unroll
        for (int kk = 0; kk < 16; kk++) {
            float4 a0 = *(const float4*)&As[buf][kk][tm];
            float4 a1 = *(const float4*)&As[buf][kk][tm + 4];
            ulonglong2 wlo = *(const ulonglong2*)&Ws[buf][kk][tn];
            ulonglong2 whi = *(const ulonglong2*)&Ws[buf][kk][tn + 4];
            float am[8] = {a0.x, a0.y, a0.z, a0.w, a1.x, a1.y, a1.z, a1.w};
            #pragma unroll
            for (int i = 0; i < 8; i++) {
                ull ad = packf2(am[i], am[i]);
                ffma2(acc[i * 4 + 0], ad, wlo.x);
                ffma2(acc[i * 4 + 1], ad, wlo.y);
                ffma2(acc[i * 4 + 2], ad, whi.x);
                ffma2(acc[i * 4 + 3], ad, whi.y);
            }
        }
        if (more) {
            __syncthreads();
            ldg_store(buf ^ 1, kBase + (it + 1) * 16);
            __syncthreads();
        }
    }

    #pragma unroll
    for (int i = 0; i < 8; i++) {
        float2 v0 = unpackf2(acc[i * 4 + 0]);
        float2 v1 = unpackf2(acc[i * 4 + 1]);
        float2 v2 = unpackf2(acc[i * 4 + 2]);
        float2 v3 = unpackf2(acc[i * 4 + 3]);
        float* row = Cp + (long)(mBase + tm + i) * N + nBase + tn;
        *(float4*)(row)     = make_float4(v0.x, v0.y, v1.x, v1.y);
        *(float4*)(row + 4) = make_float4(v2.x, v2.y, v3.x, v3.y);
    }
}

// ---------------- gate GEMMs: W_ih (compact changed) + W_hh (all rows) ------
// 160 blocks x 128 thr. t<128: IH (8n x 8sp x 2 strips, 12 slabs, K=1536,
// early-exit past chgcnt). t>=128: HH (8n x 2sp x 2 strips, 8 slabs, K=256).
__global__ __launch_bounds__(128) void k_gemmG(int step) {
    int t = blockIdx.x;
    if (t < NB_I) {
        int strip = t / 64;
        if (strip * 64 >= (int)g_chgcnt[step]) return;
        int r = t % 64;
        int nt = r & 7, sp = r >> 3;
        gemm64(g_xIc, KIH, g_Wih, KIH,
               g_partI + (size_t)sp * BB * NTRK, NTRK,
               strip * 64, nt * 128, sp * 12 * 16, 12);
    } else {
        int t2 = t - NB_I;
        int strip = t2 / 16;
        int r = t2 % 16;
        int nt = r & 7, sp = r >> 3;
        gemm64(g_th, TRK, g_Whh, TRK,
               g_partH + (size_t)sp * BB * NTRK, NTRK,
               strip * 64, nt * 128, sp * 8 * 16, 8);
    }
}

// ---------------- compacted reduce GEMM: grid (20, 5, 2) --------------------
__global__ __launch_bounds__(128) void k_gemmRED(int step) {
    int count = (int)g_redcnt[step];
    int mBase = blockIdx.z * 64;
    if (mBase >= count) return;
    int nt = blockIdx.x, sp = blockIdx.y;
    gemm64(g_xRc, KRED, g_Wred, KRED,
           g_partRc + (size_t)sp * BB * NRED, NRED,
           mBase, nt * 128, sp * 16 * 16, 16);
}

// ---------------- cell: 1024 thr, 4-way slot groups + LSTM + argmax ---------
__global__ __launch_bounds__(1024) void k_cell(const float* __restrict__ W_trans,
                                               const float* __restrict__ b_trans,
                                               float* __restrict__ out, int step) {
    int b = blockIdx.x, tid = threadIdx.x;   // 1024 threads
    __shared__ __align__(16) float part[4][NTRK];
    __shared__ float sp4[4][8];
    __shared__ int s_i;
    int ci = g_chgidx[b];
    {
        int g = (tid & 255) * 4;
        int h = tid >> 8;                    // 4 slot groups
        float4 s = make_float4(0.f, 0.f, 0.f, 0.f);
        if (h == 0) {                        // bias + 2 W_hh partials
            s = *(const float4*)&g_btrk[g];
            #pragma unroll
            for (int sp = 0; sp < SPH; sp++) {
                float4 v = *(const float4*)&g_partH[((size_t)sp * BB + b) * NTRK + g];
                s.x += v.x; s.y += v.y; s.z += v.z; s.w += v.w;
            }
        } else if (ci >= 0) {                // partI groups: 0-2 / 3-5 / 6-7
            int s0 = (h - 1) * 3;
            int s1 = s0 + 3 < SPI ? s0 + 3 : SPI;
            for (int sp = s0; sp < s1; sp++) {
                float4 v = *(const float4*)&g_partI[((size_t)sp * BB + ci) * NTRK + g];
                s.x += v.x; s.y += v.y; s.z += v.z; s.w += v.w;
            }
        } else if (h == 1) {                 // unchanged: cached W_ih . x
            s = *(const float4*)&g_gih[b * NTRK + g];
        }
        *(float4*)&part[h][g] = s;
    }
    __syncthreads();

    // cache refresh for changed rows: one column per thread
    if (ci >= 0)
        g_gih[b * NTRK + tid] = part[1][tid] + part[2][tid] + part[3][tid];

    int sptr = g_sptr[b];
    float thn = 0.f;
    if (tid < 256) {
        int j = tid;
        float gi = part[0][j] + part[1][j] + part[2][j] + part[3][j];
        float gf = part[0][TRK + j] + part[1][TRK + j] + part[2][TRK + j] + part[3][TRK + j];
        float gg = part[0][2 * TRK + j] + part[1][2 * TRK + j] + part[2][2 * TRK + j] + part[3][2 * TRK + j];
        float go = part[0][3 * TRK + j] + part[1][3 * TRK + j] + part[2][3 * TRK + j] + part[3][3 * TRK + j];
        float tc = g_tc[b * TRK + j];
        float tcn = sigf(gf) * tc + sigf(gi) * tanhf(gg);
        thn = sigf(go) * tanhf(tcn);
        g_tc[b * TRK + j] = tcn;
        g_th[b * TRK + j] = thn;     // input for next step's W_hh GEMM

        float p0 = thn * W_trans[0 * TRK + j];
        float p1 = thn * W_trans[1 * TRK + j];
        float p2 = thn * W_trans[2 * TRK + j];
        float p3 = thn * W_trans[3 * TRK + j];
        #pragma unroll
        for (int off = 16; off > 0; off >>= 1) {
            p0 += __shfl_down_sync(0xffffffffu, p0, off);
            p1 += __shfl_down_sync(0xffffffffu, p1, off);
            p2 += __shfl_down_sync(0xffffffffu, p2, off);
            p3 += __shfl_down_sync(0xffffffffu, p3, off);
        }
        if ((tid & 31) == 0) {
            int w = tid >> 5;
            sp4[0][w] = p0; sp4[1][w] = p1; sp4[2][w] = p2; sp4[3][w] = p3;
        }
    }
    __syncthreads();
    if (tid == 0) {
        float l[4];
        #pragma unroll
        for (int t = 0; t < 4; t++) {
            float s = b_trans[t];
            #pragma unroll
            for (int w = 0; w < 8; w++) s += sp4[t][w];
            l[t] = s;
        }
        float* o = out + ((long)step * BB + b) * 4;
        o[0] = l[0]; o[1] = l[1]; o[2] = l[2]; o[3] = l[3];
        int best = 0; float bv = l[0];                     // jnp.argmax: first max
        if (l[1] > bv) { bv = l[1]; best = 1; }
        if (l[2] > bv) { bv = l[2]; best = 2; }
        if (l[3] > bv) { bv = l[3]; best = 3; }
        g_trans[b] = best;
        int i = -1;
        if (best == 2 && sptr > 3) i = (int)atomicAdd(&g_redcnt[step], 1u);
        g_redidx[b] = i;
        s_i = i;
    }
    __syncthreads();
    int i = s_i;
    if (i >= 0) {   // build compacted reduce-GEMM row [s2_h | s1_h | th]
        const float* st = g_stack + (long)b * CAP * TWOD;
        float* xr = g_xRc + (size_t)i * KRED;
        if (tid < DD) {
            xr[tid]      = st[(sptr - 2) * TWOD + tid];
            xr[DD + tid] = st[(sptr - 1) * TWOD + tid];
        } else if (tid < DD + TRK) {
            int j = tid - DD;
            xr[2 * DD + j] = g_th[b * TRK + j];
        }
    }
}

// ---------------- epi: node + stack update + compact changed-row gather -----
__global__ __launch_bounds__(640) void k_epi(const float* __restrict__ buffers,
                                             const float* __restrict__ b_left, int step) {
    __shared__ __align__(16) float lin[NRED];
    __shared__ int s_ni;
    int b = blockIdx.x, tid = threadIdx.x;   // 640 threads
    int sptr = g_sptr[b], blen = g_blen[b];
    int tr = g_trans[b];
    bool do_shift = (tr == 3) && (blen > 2);
    bool do_red   = (tr == 2) && (sptr > 3);
    int ridx = g_redidx[b];

    if (do_red) {
        int c4 = tid * 4;                    // covers all 2560 columns
        float4 s = *(const float4*)&b_left[c4];
        #pragma unroll
        for (int sp = 0; sp < SPLIT_RED; sp++) {
            float4 v = *(const float4*)&g_partRc[((size_t)sp * BB + ridx) * NRED + c4];
            s.x += v.x; s.y += v.y; s.z += v.z; s.w += v.w;
        }
        *(float4*)&lin[c4] = s;
    }
    __syncthreads();

    float* st = g_stack + (long)b * CAP * TWOD;
    const float* bt = buffers + ((long)b * TT + (blen - 1)) * TWOD;

    if (do_red && tid < DD) {
        int dd = tid;
        float a  = lin[dd];
        float i_ = lin[DD + dd];
        float f1 = lin[2 * DD + dd];
        float f2 = lin[3 * DD + dd];
        float o_ = lin[4 * DD + dd];
        float s2c = st[(sptr - 2) * TWOD + DD + dd];
        float s1c = st[(sptr - 1) * TWOD + DD + dd];
        float c = tanhf(a) * sigf(i_) + sigf(f1) * s2c + sigf(f2) * s1c;
        float h = sigf(o_) * tanhf(c);
        st[(sptr - 2) * TWOD + dd]      = h;
        st[(sptr - 2) * TWOD + DD + dd] = c;
    }
    if (do_shift && tid < DD) {
        st[sptr * TWOD + tid]      = bt[tid];
        st[sptr * TWOD + DD + tid] = bt[DD + tid];
    }
    int nsp = sptr + (do_shift ? 1 : 0) - (do_red ? 1 : 0);
    int nbl = blen - (do_shift ? 1 : 0);
    bool changed = do_shift || do_red;
    if (tid == 0) {
        g_sptr[b] = nsp; g_blen[b] = nbl;
        int ni = -1;
        if (changed) ni = (int)atomicAdd(&g_chgcnt[step + 1], 1u);
        g_chgidx[b] = ni;
        s_ni = ni;
    }
    __syncthreads();

    // compact gather of the changed row's new [buf|s1|s2] for next gemmG
    int ni = s_ni;
    if (ni >= 0 && tid < DD) {
        const float* nbt = buffers + ((long)b * TT + (nbl - 1)) * TWOD;
        const float* s1 = st + (nsp - 1) * TWOD;
        const float* s2 = st + (nsp - 2) * TWOD;
        float* xi = g_xIc + (size_t)ni * KIH;
        xi[tid] = nbt[tid]; xi[DD + tid] = s1[tid]; xi[2 * DD + tid] = s2[tid];
    }
}

// ---------------------------------------------------------------------------
extern "C" void kernel_launch(void* const* d_in, const int* in_sizes, int n_in,
                              void* d_out, int out_size) {
    const float* buffers = (const float*)d_in[0];
    const float* W_left  = (const float*)d_in[1];
    const float* b_left  = (const float*)d_in[2];
    const float* W_right = (const float*)d_in[3];
    const float* W_track = (const float*)d_in[4];
    const float* W_ih    = (const float*)d_in[5];
    const float* W_hh    = (const float*)d_in[6];
    const float* b_ih    = (const float*)d_in[7];
    const float* b_hh    = (const float*)d_in[8];
    const float* W_trans = (const float*)d_in[9];
    const float* b_trans = (const float*)d_in[10];
    int n_steps = in_sizes[11] / BB;       // transitions: [n_steps, B]
    float* out = (float*)d_out;

    k_init<<<592, 256>>>(buffers, W_ih, W_hh, b_ih, b_hh, W_left, W_right, W_track);
    k_prep<<<BB, 512>>>(buffers);

    for (int s = 0; s < n_steps; s++) {
        bool more = (s + 1 < n_steps);
        k_gemmG<<<NB_G, 128>>>(s);
        k_cell<<<BB, 1024>>>(W_trans, b_trans, out, s);
        if (more) {
            k_gemmRED<<<dim3(20, SPLIT_RED, 2), 128>>>(s);
            k_epi<<<BB, 640>>>(buffers, b_left, s);
        }
    }
}

// round 17
// speedup vs baseline: 1.0684x; 1.0684x over previous
#include <cuda_runtime.h>
#include <math.h>

// Problem constants (SPINN1: B=128, T=40, D_HID=512, D_TRK=256)
#define BB   128
#define TT   40
#define DD   512
#define TRK  256
#define CAP  (TT + 2)            // 42
#define TWOD (2 * DD)            // 1024
#define KIH  (3 * DD)            // 1536  (xIc = [buf_h | s1_h | s2_h])
#define NTRK (4 * TRK)           // 1024
#define KRED (2 * DD + TRK)      // 1280  (xRc row = [s2_h | s1_h | th_new])
#define NRED (5 * DD)            // 2560
#define SPI  12                  // W_ih compact GEMM split-K (8 slabs each)
#define SPH  2                   // W_hh GEMM split-K (8 slabs each)
#define SPLIT_RED 10             // reduce split-K (8 slabs each)
#define NB_I (8 * SPI * 2)       // 192 IH blocks (2 m-strips, early-exit)
#define NB_H (8 * SPH * 2)       // 32 HH blocks
#define NB_G (NB_I + NB_H)       // 224
#define MAXSTEPS 64

// ---------------- device state (no runtime allocation allowed) --------------
__device__ __align__(16) float g_stack[BB * CAP * TWOD];
__device__ __align__(16) float g_th[BB * TRK];
__device__ __align__(16) float g_tc[BB * TRK];
__device__ int   g_sptr[BB];
__device__ int   g_blen[BB];
__device__ __align__(16) float g_xIc[BB * KIH];           // COMPACTED changed rows
__device__ __align__(16) float g_xRc[BB * KRED];          // COMPACTED reduce rows
__device__ __align__(16) float g_gih[BB * NTRK];          // cached W_ih . x per row
__device__ __align__(16) float g_partI[SPI * BB * NTRK];
__device__ __align__(16) float g_partH[SPH * BB * NTRK];
__device__ __align__(16) float g_partRc[SPLIT_RED * BB * NRED];
__device__ int   g_trans[BB];
__device__ int   g_redidx[BB];                            // reduce compact idx or -1
__device__ int   g_chgidx[BB];                            // changed compact idx or -1
__device__ unsigned g_redcnt[MAXSTEPS];
__device__ unsigned g_chgcnt[MAXSTEPS + 1];
__device__ __align__(16) float g_Wih[NTRK * KIH];
__device__ __align__(16) float g_Whh[NTRK * TRK];
__device__ __align__(16) float g_Wred[NRED * KRED];  // [W_left | W_right | W_track]
__device__ __align__(16) float g_btrk[NTRK];         // b_ih + b_hh

__device__ __forceinline__ float sigf(float x) { return 1.0f / (1.0f + expf(-x)); }

typedef unsigned long long ull;
__device__ __forceinline__ ull packf2(float x, float y) {
    ull v; asm("mov.b64 %0, {%1,%2};" : "=l"(v) : "f"(x), "f"(y)); return v;
}
__device__ __forceinline__ float2 unpackf2(ull v) {
    float2 r; asm("mov.b64 {%0,%1}, %2;" : "=f"(r.x), "=f"(r.y) : "l"(v)); return r;
}
__device__ __forceinline__ void ffma2(ull& d, ull a, ull b) {
    asm("fma.rn.f32x2 %0, %1, %2, %0;" : "+l"(d) : "l"(a), "l"(b));
}

// ---------------- init -------------------------------------------------------
__global__ void k_init(const float* __restrict__ buffers,
                       const float* __restrict__ W_ih, const float* __restrict__ W_hh,
                       const float* __restrict__ b_ih, const float* __restrict__ b_hh,
                       const float* __restrict__ W_left, const float* __restrict__ W_right,
                       const float* __restrict__ W_track) {
    int stride = gridDim.x * blockDim.x;
    int tid0 = blockIdx.x * blockDim.x + threadIdx.x;

    for (int idx = tid0; idx < NTRK * KIH; idx += stride) g_Wih[idx] = W_ih[idx];
    for (int idx = tid0; idx < NTRK * TRK; idx += stride) g_Whh[idx] = W_hh[idx];
    for (int idx = tid0; idx < NRED * KRED; idx += stride) {
        int n = idx / KRED, k = idx - n * KRED;
        float v;
        if (k < DD)            v = W_left[n * DD + k];
        else if (k < 2 * DD)   v = W_right[n * DD + (k - DD)];
        else                   v = W_track[n * TRK + (k - 2 * DD)];
        g_Wred[idx] = v;
    }
    for (int idx = tid0; idx < NTRK; idx += stride) g_btrk[idx] = b_ih[idx] + b_hh[idx];
    for (int idx = tid0; idx < BB * TWOD; idx += stride) {
        int b = idx / TWOD, j = idx - b * TWOD;
        float v = buffers[(long)b * TT * TWOD + j];   // buffers[b, 0, j]
        g_stack[((long)b * CAP + 0) * TWOD + j] = v;
        g_stack[((long)b * CAP + 1) * TWOD + j] = v;
    }
    for (int idx = tid0; idx < BB * TRK; idx += stride) { g_th[idx] = 0.f; g_tc[idx] = 0.f; }
    for (int idx = tid0; idx < BB; idx += stride) {
        g_sptr[idx] = 2; g_blen[idx] = TT; g_redidx[idx] = -1; g_chgidx[idx] = -1;
    }
    for (int idx = tid0; idx < MAXSTEPS; idx += stride) g_redcnt[idx] = 0u;
    for (int idx = tid0; idx <= MAXSTEPS; idx += stride) g_chgcnt[idx] = 0u;
}

// ---------------- prep: step 0 treats every row as changed ------------------
__global__ void k_prep(const float* __restrict__ buffers) {
    int b = blockIdx.x, tid = threadIdx.x;    // 512 threads
    int sptr = g_sptr[b], blen = g_blen[b];
    const float* bt = buffers + ((long)b * TT + (blen - 1)) * TWOD;
    const float* s1 = g_stack + ((long)b * CAP + (sptr - 1)) * TWOD;
    const float* s2 = g_stack + ((long)b * CAP + (sptr - 2)) * TWOD;
    float* xi = g_xIc + (size_t)b * KIH;      // compact idx = b at step 0
    xi[tid] = bt[tid]; xi[DD + tid] = s1[tid]; xi[2 * DD + tid] = s2[tid];
    if (tid == 0) { g_chgidx[b] = b; g_chgcnt[0] = (unsigned)BB; }
}

// ---------------- BM=64 GEMM tile (128 thr, 8x8 microtile, fp32x2) ----------
__device__ __forceinline__ void gemm64(const float* __restrict__ A, int lda,
                                       const float* __restrict__ W, int ldw,
                                       float* __restrict__ Cp, int N,
                                       int mBase, int nBase, int kBase, int iters) {
    __shared__ __align__(16) float As[2][16][64];
    __shared__ __align__(16) float Ws[2][16][128];
    int tid = threadIdx.x;           // 128 threads
    int tm = (tid & 7) * 8;          // 8 m-groups
    int tn = (tid >> 3) * 8;         // 16 n-groups
    int row4 = tid >> 2;
    int lk   = (tid & 3) * 4;

    ull acc[32];
    #pragma unroll
    for (int i = 0; i < 32; i++) acc[i] = 0ull;

    auto ldg_store = [&](int buf, int k0) {
        #pragma unroll
        for (int r = 0; r < 2; r++) {      // A: 64 rows
            int row = row4 + r * 32;
            float4 v = *(const float4*)(A + (long)(mBase + row) * lda + k0 + lk);
            As[buf][lk + 0][row] = v.x; As[buf][lk + 1][row] = v.y;
            As[buf][lk + 2][row] = v.z; As[buf][lk + 3][row] = v.w;
        }
        #pragma unroll
        for (int r = 0; r < 4; r++) {      // W: 128 rows
            int row = row4 + r * 32;
            float4 v = *(const float4*)(W + (long)(nBase + row) * ldw + k0 + lk);
            Ws[buf][lk + 0][row] = v.x; Ws[buf][lk + 1][row] = v.y;
            Ws[buf][lk + 2][row] = v.z; Ws[buf][lk + 3][row] = v.w;
        }
    };

    ldg_store(0, kBase);
    __syncthreads();

    for (int it = 0; it < iters; it++) {
        int buf = it & 1;
        bool more = (it + 1) < iters;
        #pragma unroll
        for (int kk = 0; kk < 16; kk++) {
            float4 a0 = *(const float4*)&As[buf][kk][tm];
            float4 a1 = *(const float4*)&As[buf][kk][tm + 4];
            ulonglong2 wlo = *(const ulonglong2*)&Ws[buf][kk][tn];
            ulonglong2 whi = *(const ulonglong2*)&Ws[buf][kk][tn + 4];
            float am[8] = {a0.x, a0.y, a0.z, a0.w, a1.x, a1.y, a1.z, a1.w};
            #pragma unroll
            for (int i = 0; i < 8; i++) {
                ull ad = packf2(am[i], am[i]);
                ffma2(acc[i * 4 + 0], ad, wlo.x);
                ffma2(acc[i * 4 + 1], ad, wlo.y);
                ffma2(acc[i * 4 + 2], ad, whi.x);
                ffma2(acc[i * 4 + 3], ad, whi.y);
            }
        }
        if (more) {
            __syncthreads();
            ldg_store(buf ^ 1, kBase + (it + 1) * 16);
            __syncthreads();
        }
    }

    #pragma unroll
    for (int i = 0; i < 8; i++) {
        float2 v0 = unpackf2(acc[i * 4 + 0]);
        float2 v1 = unpackf2(acc[i * 4 + 1]);
        float2 v2 = unpackf2(acc[i * 4 + 2]);
        float2 v3 = unpackf2(acc[i * 4 + 3]);
        float* row = Cp + (long)(mBase + tm + i) * N + nBase + tn;
        *(float4*)(row)     = make_float4(v0.x, v0.y, v1.x, v1.y);
        *(float4*)(row + 4) = make_float4(v2.x, v2.y, v3.x, v3.y);
    }
}

// ---------------- gate GEMMs: W_ih (compact changed) + W_hh (all rows) ------
// 224 blocks x 128 thr. t<192: IH (8n x 12sp x 2 strips, 8 slabs, K=1536,
// early-exit past chgcnt). t>=192: HH (8n x 2sp x 2 strips, 8 slabs, K=256).
__global__ __launch_bounds__(128) void k_gemmG(int step) {
    int t = blockIdx.x;
    if (t < NB_I) {
        int strip = t / 96;
        if (strip * 64 >= (int)g_chgcnt[step]) return;
        int r = t % 96;
        int nt = r & 7, sp = r >> 3;
        gemm64(g_xIc, KIH, g_Wih, KIH,
               g_partI + (size_t)sp * BB * NTRK, NTRK,
               strip * 64, nt * 128, sp * 8 * 16, 8);
    } else {
        int t2 = t - NB_I;
        int strip = t2 / 16;
        int r = t2 % 16;
        int nt = r & 7, sp = r >> 3;
        gemm64(g_th, TRK, g_Whh, TRK,
               g_partH + (size_t)sp * BB * NTRK, NTRK,
               strip * 64, nt * 128, sp * 8 * 16, 8);
    }
}

// ---------------- compacted reduce GEMM: grid (20, 10, 2) -------------------
__global__ __launch_bounds__(128) void k_gemmRED(int step) {
    int count = (int)g_redcnt[step];
    int mBase = blockIdx.z * 64;
    if (mBase >= count) return;
    int nt = blockIdx.x, sp = blockIdx.y;
    gemm64(g_xRc, KRED, g_Wred, KRED,
           g_partRc + (size_t)sp * BB * NRED, NRED,
           mBase, nt * 128, sp * 8 * 16, 8);
}

// ---------------- cell: balanced slot groups + LSTM + argmax + xRc ----------
__global__ __launch_bounds__(512) void k_cell(const float* __restrict__ W_trans,
                                              const float* __restrict__ b_trans,
                                              float* __restrict__ out, int step) {
    int b = blockIdx.x, tid = threadIdx.x;   // 512 threads
    __shared__ __align__(16) float part[2][NTRK];
    __shared__ float sp4[4][8];
    __shared__ int s_i;
    int ci = g_chgidx[b];
    {
        int g = (tid & 255) * 4;
        int h = tid >> 8;
        float4 s;
        if (h == 0) {            // bias + 2 partH (+ partI 0..3 if changed)
            s = *(const float4*)&g_btrk[g];
            #pragma unroll
            for (int sp = 0; sp < SPH; sp++) {
                float4 v = *(const float4*)&g_partH[((size_t)sp * BB + b) * NTRK + g];
                s.x += v.x; s.y += v.y; s.z += v.z; s.w += v.w;
            }
            if (ci >= 0) {
                #pragma unroll
                for (int sp = 0; sp < 4; sp++) {
                    float4 v = *(const float4*)&g_partI[((size_t)sp * BB + ci) * NTRK + g];
                    s.x += v.x; s.y += v.y; s.z += v.z; s.w += v.w;
                }
            }
        } else {                 // partI 4..11 (changed) or cached gih
            if (ci >= 0) {
                s = make_float4(0.f, 0.f, 0.f, 0.f);
                #pragma unroll
                for (int sp = 4; sp < SPI; sp++) {
                    float4 v = *(const float4*)&g_partI[((size_t)sp * BB + ci) * NTRK + g];
                    s.x += v.x; s.y += v.y; s.z += v.z; s.w += v.w;
                }
            } else {
                s = *(const float4*)&g_gih[b * NTRK + g];
            }
        }
        *(float4*)&part[h][g] = s;
    }
    __syncthreads();

    // cache refresh for changed rows: g_gih = full W_ih.x (part sums minus bias/HH
    // would be wrong; recompute as partI totals = (part0 - bias - HH) + part1).
    if (ci >= 0) {
        int g = (tid & 255) * 4;
        if ((tid >> 8) == 1) {
            float4 tot = *(const float4*)&part[1][g];
            #pragma unroll
            for (int sp = 0; sp < 4; sp++) {
                float4 v = *(const float4*)&g_partI[((size_t)sp * BB + ci) * NTRK + g];
                tot.x += v.x; tot.y += v.y; tot.z += v.z; tot.w += v.w;
            }
            *(float4*)&g_gih[b * NTRK + g] = tot;
        }
    }

    int sptr = g_sptr[b];
    float thn = 0.f;
    if (tid < 256) {
        int j = tid;
        float gi = part[0][j] + part[1][j];
        float gf = part[0][TRK + j] + part[1][TRK + j];
        float gg = part[0][2 * TRK + j] + part[1][2 * TRK + j];
        float go = part[0][3 * TRK + j] + part[1][3 * TRK + j];
        float tc = g_tc[b * TRK + j];
        float tcn = sigf(gf) * tc + sigf(gi) * tanhf(gg);
        thn = sigf(go) * tanhf(tcn);
        g_tc[b * TRK + j] = tcn;
        g_th[b * TRK + j] = thn;     // input for next step's W_hh GEMM

        float p0 = thn * W_trans[0 * TRK + j];
        float p1 = thn * W_trans[1 * TRK + j];
        float p2 = thn * W_trans[2 * TRK + j];
        float p3 = thn * W_trans[3 * TRK + j];
        #pragma unroll
        for (int off = 16; off > 0; off >>= 1) {
            p0 += __shfl_down_sync(0xffffffffu, p0, off);
            p1 += __shfl_down_sync(0xffffffffu, p1, off);
            p2 += __shfl_down_sync(0xffffffffu, p2, off);
            p3 += __shfl_down_sync(0xffffffffu, p3, off);
        }
        if ((tid & 31) == 0) {
            int w = tid >> 5;
            sp4[0][w] = p0; sp4[1][w] = p1; sp4[2][w] = p2; sp4[3][w] = p3;
        }
    }
    __syncthreads();
    if (tid == 0) {
        float l[4];
        #pragma unroll
        for (int t = 0; t < 4; t++) {
            float s = b_trans[t];
            #pragma unroll
            for (int w = 0; w < 8; w++) s += sp4[t][w];
            l[t] = s;
        }
        float* o = out + ((long)step * BB + b) * 4;
        o[0] = l[0]; o[1] = l[1]; o[2] = l[2]; o[3] = l[3];
        int best = 0; float bv = l[0];                     // jnp.argmax: first max
        if (l[1] > bv) { bv = l[1]; best = 1; }
        if (l[2] > bv) { bv = l[2]; best = 2; }
        if (l[3] > bv) { bv = l[3]; best = 3; }
        g_trans[b] = best;
        int i = -1;
        if (best == 2 && sptr > 3) i = (int)atomicAdd(&g_redcnt[step], 1u);
        g_redidx[b] = i;
        s_i = i;
    }
    __syncthreads();
    int i = s_i;
    if (i >= 0) {   // build compacted reduce-GEMM row [s2_h | s1_h | th]
        const float* st = g_stack + (long)b * CAP * TWOD;
        float* xr = g_xRc + (size_t)i * KRED;
        xr[tid]       = st[(sptr - 2) * TWOD + tid];
        xr[DD + tid]  = st[(sptr - 1) * TWOD + tid];
        if (tid < TRK) xr[2 * DD + tid] = g_th[b * TRK + tid];
    }
}

// ---------------- epi: node + stack update + compact changed-row gather -----
__global__ __launch_bounds__(640) void k_epi(const float* __restrict__ buffers,
                                             const float* __restrict__ b_left, int step) {
    __shared__ __align__(16) float lin[NRED];
    __shared__ int s_ni;
    int b = blockIdx.x, tid = threadIdx.x;   // 640 threads
    int sptr = g_sptr[b], blen = g_blen[b];
    int tr = g_trans[b];
    bool do_shift = (tr == 3) && (blen > 2);
    bool do_red   = (tr == 2) && (sptr > 3);
    int ridx = g_redidx[b];

    if (do_red) {
        int c4 = tid * 4;                    // covers all 2560 columns
        float4 s = *(const float4*)&b_left[c4];
        #pragma unroll
        for (int sp = 0; sp < SPLIT_RED; sp++) {
            float4 v = *(const float4*)&g_partRc[((size_t)sp * BB + ridx) * NRED + c4];
            s.x += v.x; s.y += v.y; s.z += v.z; s.w += v.w;
        }
        *(float4*)&lin[c4] = s;
    }
    __syncthreads();

    float* st = g_stack + (long)b * CAP * TWOD;
    const float* bt = buffers + ((long)b * TT + (blen - 1)) * TWOD;

    if (do_red && tid < DD) {
        int dd = tid;
        float a  = lin[dd];
        float i_ = lin[DD + dd];
        float f1 = lin[2 * DD + dd];
        float f2 = lin[3 * DD + dd];
        float o_ = lin[4 * DD + dd];
        float s2c = st[(sptr - 2) * TWOD + DD + dd];
        float s1c = st[(sptr - 1) * TWOD + DD + dd];
        float c = tanhf(a) * sigf(i_) + sigf(f1) * s2c + sigf(f2) * s1c;
        float h = sigf(o_) * tanhf(c);
        st[(sptr - 2) * TWOD + dd]      = h;
        st[(sptr - 2) * TWOD + DD + dd] = c;
    }
    if (do_shift && tid < DD) {
        st[sptr * TWOD + tid]      = bt[tid];
        st[sptr * TWOD + DD + tid] = bt[DD + tid];
    }
    int nsp = sptr + (do_shift ? 1 : 0) - (do_red ? 1 : 0);
    int nbl = blen - (do_shift ? 1 : 0);
    bool changed = do_shift || do_red;
    if (tid == 0) {
        g_sptr[b] = nsp; g_blen[b] = nbl;
        int ni = -1;
        if (changed) ni = (int)atomicAdd(&g_chgcnt[step + 1], 1u);
        g_chgidx[b] = ni;
        s_ni = ni;
    }
    __syncthreads();

    // compact gather of the changed row's new [buf|s1|s2] for next gemmG
    int ni = s_ni;
    if (ni >= 0 && tid < DD) {
        const float* nbt = buffers + ((long)b * TT + (nbl - 1)) * TWOD;
        const float* s1 = st + (nsp - 1) * TWOD;
        const float* s2 = st + (nsp - 2) * TWOD;
        float* xi = g_xIc + (size_t)ni * KIH;
        xi[tid] = nbt[tid]; xi[DD + tid] = s1[tid]; xi[2 * DD + tid] = s2[tid];
    }
}

// ---------------------------------------------------------------------------
extern "C" void kernel_launch(void* const* d_in, const int* in_sizes, int n_in,
                              void* d_out, int out_size) {
    const float* buffers = (const float*)d_in[0];
    const float* W_left  = (const float*)d_in[1];
    const float* b_left  = (const float*)d_in[2];
    const float* W_right = (const float*)d_in[3];
    const float* W_track = (const float*)d_in[4];
    const float* W_ih    = (const float*)d_in[5];
    const float* W_hh    = (const float*)d_in[6];
    const float* b_ih    = (const float*)d_in[7];
    const float* b_hh    = (const float*)d_in[8];
    const float* W_trans = (const float*)d_in[9];
    const float* b_trans = (const float*)d_in[10];
    int n_steps = in_sizes[11] / BB;       // transitions: [n_steps, B]
    float* out = (float*)d_out;

    k_init<<<592, 256>>>(buffers, W_ih, W_hh, b_ih, b_hh, W_left, W_right, W_track);
    k_prep<<<BB, 512>>>(buffers);

    for (int s = 0; s < n_steps; s++) {
        bool more = (s + 1 < n_steps);
        k_gemmG<<<NB_G, 128>>>(s);
        k_cell<<<BB, 512>>>(W_trans, b_trans, out, s);
        if (more) {
            k_gemmRED<<<dim3(20, SPLIT_RED, 2), 128>>>(s);
            k_epi<<<BB, 640>>>(buffers, b_left, s);
        }
    }
}